// round 9
// baseline (speedup 1.0000x reference)
#include <cuda_runtime.h>
#include <cuda_bf16.h>
#include <math.h>

#define N_NODES 81
#define N_EDGES 1620
#define IN_DIM 10
#define HIDDEN 8192
#define ACTIONS 729

// j-chunks (of 64 rows) of W1 read with default .ca loads (L2-resident part).
// 48 * 64 = 3072 rows = 96 MB pinned; remaining 160 MB streamed with __ldcs.
// Budget: 96 (W1 pin) + 24 (W2) + 2.7 (pre) ≈ 123 MB < 126 MB L2.
#define PIN_CHUNKS 48

// ---- scratch (no allocs allowed; __device__ globals) ----
__device__ float d_agg[N_NODES * IN_DIM];       // Â x  (input-space aggregate)
__device__ float d_pre[N_NODES * HIDDEN];       // relu(gcn) pre-LN
__device__ float d_nsum[N_NODES];               // per-node sum
__device__ float d_nsq[N_NODES];                // per-node sum of squares
__device__ float d_g[HIDDEN];                   // pooled vector
__device__ float d_y1[HIDDEN];                  // g @ W1 accumulator
__device__ float d_logits[736];                 // y1r @ W2 accumulator

// ============================================================
// K1: degrees, norms, input-space aggregation; zero accumulators
// edge_index dtype detected at runtime (int32 vs int64):
// int64 viewed as int32 pairs has all-zero high words (values < 81).
// ============================================================
__global__ void k_setup(const float* __restrict__ x,
                        const int* __restrict__ ei32) {
    __shared__ float s_deg[N_NODES];
    __shared__ float s_dinv[N_NODES];
    __shared__ float s_agg[N_NODES * IN_DIM];
    __shared__ int s_is64;
    int t = threadIdx.x;

    // zero the cross-launch accumulators (graph replays re-run this first)
    for (int i = t; i < HIDDEN; i += 256) d_y1[i] = 0.f;
    for (int i = t; i < 736; i += 256) d_logits[i] = 0.f;
    if (t < N_NODES) { d_nsum[t] = 0.f; d_nsq[t] = 0.f; }

    if (t == 0) {
        int any = 0;
        #pragma unroll 8
        for (int i = 0; i < 128; i++) any |= ei32[2 * i + 1];
        s_is64 = (any == 0) ? 1 : 0;   // all high words zero -> int64
    }
    if (t < N_NODES) s_deg[t] = 1.f;  // self-loop
    for (int i = t; i < N_NODES * IN_DIM; i += 256) s_agg[i] = 0.f;
    __syncthreads();
    const int is64 = s_is64;

    for (int e = t; e < N_EDGES; e += 256) {
        int d = is64 ? ei32[2 * (N_EDGES + e)] : ei32[N_EDGES + e];
        atomicAdd(&s_deg[d], 1.f);
    }
    __syncthreads();

    if (t < N_NODES) s_dinv[t] = rsqrtf(s_deg[t]);
    __syncthreads();

    for (int e = t; e < N_EDGES; e += 256) {
        int s = is64 ? ei32[2 * e] : ei32[e];
        int d = is64 ? ei32[2 * (N_EDGES + e)] : ei32[N_EDGES + e];
        float nm = s_dinv[s] * s_dinv[d];
        #pragma unroll
        for (int k = 0; k < IN_DIM; k++)
            atomicAdd(&s_agg[d * IN_DIM + k], nm * x[s * IN_DIM + k]);
    }
    if (t < N_NODES) {
        float nm = s_dinv[t] * s_dinv[t];  // self-loop message
        #pragma unroll
        for (int k = 0; k < IN_DIM; k++)
            atomicAdd(&s_agg[t * IN_DIM + k], nm * x[t * IN_DIM + k]);
    }
    __syncthreads();

    for (int i = t; i < N_NODES * IN_DIM; i += 256) d_agg[i] = s_agg[i];
}

// ============================================================
// K2: pre[n][j] = relu(agg[n] . W_gcn[:,j] + b_gcn[j])
//     grid (32 j-chunks x 9 node-chunks) = 288 blocks
// ============================================================
__global__ void __launch_bounds__(256) k_gcn(const float* __restrict__ Wg,
                                             const float* __restrict__ bg) {
    __shared__ float s_agg[N_NODES * IN_DIM];
    int t = threadIdx.x;
    for (int i = t; i < N_NODES * IN_DIM; i += 256) s_agg[i] = d_agg[i];
    __syncthreads();

    int j = blockIdx.x * 256 + t;
    int n0 = blockIdx.y * 9;
    float w[IN_DIM];
    #pragma unroll
    for (int k = 0; k < IN_DIM; k++) w[k] = Wg[k * HIDDEN + j];
    float bj = bg[j];

    #pragma unroll
    for (int nn = 0; nn < 9; nn++) {
        int n = n0 + nn;
        float acc = bj;
        #pragma unroll
        for (int k = 0; k < IN_DIM; k++)
            acc = fmaf(s_agg[n * IN_DIM + k], w[k], acc);
        d_pre[n * HIDDEN + j] = fmaxf(acc, 0.f);
    }
}

// ============================================================
// K3: per-node partial LN sums; grid (81 nodes x 4 j-chunks)
//     each block: 2048 values, warp+shared reduce, 2 global atomics
// ============================================================
__global__ void __launch_bounds__(256) k_stats() {
    int n = blockIdx.x;
    const float* row = d_pre + (size_t)n * HIDDEN + blockIdx.y * 2048;
    int t = threadIdx.x;
    float s = 0.f, q = 0.f;
    #pragma unroll
    for (int i = 0; i < 8; i++) {
        float p = row[t + i * 256];
        s += p;
        q = fmaf(p, p, q);
    }
    #pragma unroll
    for (int o = 16; o > 0; o >>= 1) {
        s += __shfl_xor_sync(0xffffffffu, s, o);
        q += __shfl_xor_sync(0xffffffffu, q, o);
    }
    __shared__ float ws[8], wq[8];
    int w = t >> 5, l = t & 31;
    if (l == 0) { ws[w] = s; wq[w] = q; }
    __syncthreads();
    if (t == 0) {
        float S = 0.f, Q = 0.f;
        #pragma unroll
        for (int i = 0; i < 8; i++) { S += ws[i]; Q += wq[i]; }
        atomicAdd(&d_nsum[n], S);
        atomicAdd(&d_nsq[n], Q);
    }
}

// ============================================================
// K4: pooled vector; grid 128 blocks, 64 j's per block,
//     4-way node split per j, shared reduce.
//   g[j] = ln_g[j]*(sum_n rinv_n*pre[n][j] - C) + 81*ln_b[j]
// ============================================================
__global__ void __launch_bounds__(256) k_pool(const float* __restrict__ lng,
                                              const float* __restrict__ lnb) {
    __shared__ float s_r[N_NODES];
    __shared__ float s_rm[N_NODES];
    __shared__ float s_part[256];
    int t = threadIdx.x;
    if (t < N_NODES) {
        float mu = d_nsum[t] * (1.f / HIDDEN);
        float var = d_nsq[t] * (1.f / HIDDEN) - mu * mu;
        float r = rsqrtf(var + 1e-5f);
        s_r[t] = r;
        s_rm[t] = r * mu;
    }
    __syncthreads();
    float C = 0.f;
    #pragma unroll
    for (int n = 0; n < N_NODES; n++) C += s_rm[n];

    int tj = t & 63;
    int grp = t >> 6;                       // 0..3
    int j = blockIdx.x * 64 + tj;
    float acc = 0.f;
    #pragma unroll 4
    for (int n = grp; n < N_NODES; n += 4)
        acc = fmaf(s_r[n], d_pre[(size_t)n * HIDDEN + j], acc);
    s_part[t] = acc;
    __syncthreads();
    if (grp == 0) {
        float a = s_part[tj] + s_part[64 + tj] + s_part[128 + tj] + s_part[192 + tj];
        d_g[j] = lng[j] * (a - C) + (float)N_NODES * lnb[j];
    }
}

// ============================================================
// K5: y1 = g @ W1   (the 256MB matvec — the whole problem)
//   grid (8 i-chunks x 128 j-chunks) = 1024 blocks, 256 threads.
//   Each thread: one float4 column, 64 rows; split-K via atomicAdd.
//   L2 residency split: first PIN_CHUNKS j-chunks use .ca loads
//   (stay L2-resident across graph replays); rest use __ldcs.
// ============================================================
__global__ void __launch_bounds__(256) k_mv1(const float* __restrict__ W1) {
    __shared__ float s_g[64];
    int t = threadIdx.x;
    int j0 = blockIdx.y * 64;
    if (t < 64) s_g[t] = d_g[j0 + t];
    __syncthreads();

    int i4 = blockIdx.x * 256 + t;               // float4 index in [0, 2048)
    const float4* W4 = (const float4*)W1;        // row stride = 2048 float4
    const float4* base = W4 + (size_t)j0 * (HIDDEN / 4) + i4;
    float4 acc = make_float4(0.f, 0.f, 0.f, 0.f);

    if (blockIdx.y < PIN_CHUNKS) {
        #pragma unroll 8
        for (int jj = 0; jj < 64; jj++) {
            float gv = s_g[jj];
            float4 w = base[(size_t)jj * (HIDDEN / 4)];
            acc.x = fmaf(gv, w.x, acc.x);
            acc.y = fmaf(gv, w.y, acc.y);
            acc.z = fmaf(gv, w.z, acc.z);
            acc.w = fmaf(gv, w.w, acc.w);
        }
    } else {
        #pragma unroll 8
        for (int jj = 0; jj < 64; jj++) {
            float gv = s_g[jj];
            float4 w = __ldcs(&base[(size_t)jj * (HIDDEN / 4)]);
            acc.x = fmaf(gv, w.x, acc.x);
            acc.y = fmaf(gv, w.y, acc.y);
            acc.z = fmaf(gv, w.z, acc.z);
            acc.w = fmaf(gv, w.w, acc.w);
        }
    }
    float* y = d_y1 + (size_t)i4 * 4;
    atomicAdd(y + 0, acc.x);
    atomicAdd(y + 1, acc.y);
    atomicAdd(y + 2, acc.z);
    atomicAdd(y + 3, acc.w);
}

// ============================================================
// K6: logits = relu(y1 + b1) @ W2   (24MB; keep .ca → L2-resident)
//   grid 128 i-chunks of 64; 736 threads (23 warps, 729 active)
// ============================================================
__global__ void __launch_bounds__(736) k_mv2(const float* __restrict__ W2,
                                             const float* __restrict__ b1) {
    __shared__ float s_y[64];
    int t = threadIdx.x;
    int i0 = blockIdx.x * 64;
    if (t < 64) {
        float v = d_y1[i0 + t] + b1[i0 + t];
        s_y[t] = fmaxf(v, 0.f);
    }
    __syncthreads();
    if (t < ACTIONS) {
        const float* w = W2 + (size_t)i0 * ACTIONS + t;
        float acc = 0.f;
        #pragma unroll 8
        for (int ii = 0; ii < 64; ii++)
            acc = fmaf(s_y[ii], __ldg(w + (size_t)ii * ACTIONS), acc);
        atomicAdd(&d_logits[t], acc);
    }
}

// ============================================================
// K7: add b2, log_softmax, write output
// ============================================================
__global__ void __launch_bounds__(1024) k_out(const float* __restrict__ b2,
                                              float* __restrict__ out) {
    __shared__ float sh[1024];
    int t = threadIdx.x;
    float l = (t < ACTIONS) ? d_logits[t] + b2[t] : -1e30f;
    sh[t] = l;
    __syncthreads();
    for (int s = 512; s > 0; s >>= 1) {
        if (t < s) sh[t] = fmaxf(sh[t], sh[t + s]);
        __syncthreads();
    }
    float m = sh[0];
    __syncthreads();
    float e = (t < ACTIONS) ? expf(l - m) : 0.f;
    sh[t] = e;
    __syncthreads();
    for (int s = 512; s > 0; s >>= 1) {
        if (t < s) sh[t] += sh[t + s];
        __syncthreads();
    }
    float lse = logf(sh[0]);
    if (t < ACTIONS) out[t] = l - m - lse;
}

// ============================================================
extern "C" void kernel_launch(void* const* d_in, const int* in_sizes, int n_in,
                              void* d_out, int out_size) {
    const float* x   = (const float*)d_in[0];
    const int*   ei  = (const int*)d_in[1];     // int32 or int64 (detected)
    const float* Wg  = (const float*)d_in[2];
    const float* bg  = (const float*)d_in[3];
    const float* lng = (const float*)d_in[4];
    const float* lnb = (const float*)d_in[5];
    const float* W1  = (const float*)d_in[6];
    const float* b1  = (const float*)d_in[7];
    const float* W2  = (const float*)d_in[8];
    const float* b2  = (const float*)d_in[9];
    float* out = (float*)d_out;

    k_setup<<<1, 256>>>(x, ei);
    k_gcn<<<dim3(32, 9), 256>>>(Wg, bg);
    k_stats<<<dim3(N_NODES, 4), 256>>>();
    k_pool<<<128, 256>>>(lng, lnb);
    k_mv1<<<dim3(8, 128), 256>>>(W1);
    k_mv2<<<128, 736>>>(W2, b1);
    k_out<<<1, 1024>>>(b2, out);
}

// round 15
// speedup vs baseline: 1.0068x; 1.0068x over previous
#include <cuda_runtime.h>
#include <cuda_bf16.h>
#include <math.h>

#define N_NODES 81
#define N_EDGES 1620
#define IN_DIM 10
#define HIDDEN 8192
#define ACTIONS 729

// j-chunks (of 256 rows) of W1 read with default .ca loads (L2-resident part).
// 12 * 256 = 3072 rows = 96 MB pinned; remaining 160 MB streamed with __ldcs.
#define PIN_CHUNKS 12

// ---- scratch (no allocs allowed; __device__ globals) ----
__device__ float d_agg[N_NODES * IN_DIM];       // Â x  (input-space aggregate)
__device__ float d_pre[N_NODES * HIDDEN];       // relu(gcn) pre-LN
__device__ float d_nsum[N_NODES];               // per-node sum
__device__ float d_nsq[N_NODES];                // per-node sum of squares
__device__ float d_g[HIDDEN];                   // pooled vector
__device__ float d_y1[HIDDEN];                  // g @ W1 accumulator
__device__ float d_logits[736];                 // y1r @ W2 accumulator

// ============================================================
// K1: degrees, norms, input-space aggregation; zero accumulators
// edge_index dtype detected at runtime (int32 vs int64).
// ============================================================
__global__ void k_setup(const float* __restrict__ x,
                        const int* __restrict__ ei32) {
    __shared__ float s_deg[N_NODES];
    __shared__ float s_dinv[N_NODES];
    __shared__ float s_agg[N_NODES * IN_DIM];
    __shared__ int s_is64;
    int t = threadIdx.x;

    for (int i = t; i < HIDDEN; i += 256) d_y1[i] = 0.f;
    for (int i = t; i < 736; i += 256) d_logits[i] = 0.f;
    if (t < N_NODES) { d_nsum[t] = 0.f; d_nsq[t] = 0.f; }

    if (t == 0) {
        int any = 0;
        #pragma unroll 8
        for (int i = 0; i < 128; i++) any |= ei32[2 * i + 1];
        s_is64 = (any == 0) ? 1 : 0;   // all high words zero -> int64
    }
    if (t < N_NODES) s_deg[t] = 1.f;  // self-loop
    for (int i = t; i < N_NODES * IN_DIM; i += 256) s_agg[i] = 0.f;
    __syncthreads();
    const int is64 = s_is64;

    for (int e = t; e < N_EDGES; e += 256) {
        int d = is64 ? ei32[2 * (N_EDGES + e)] : ei32[N_EDGES + e];
        atomicAdd(&s_deg[d], 1.f);
    }
    __syncthreads();

    if (t < N_NODES) s_dinv[t] = rsqrtf(s_deg[t]);
    __syncthreads();

    for (int e = t; e < N_EDGES; e += 256) {
        int s = is64 ? ei32[2 * e] : ei32[e];
        int d = is64 ? ei32[2 * (N_EDGES + e)] : ei32[N_EDGES + e];
        float nm = s_dinv[s] * s_dinv[d];
        #pragma unroll
        for (int k = 0; k < IN_DIM; k++)
            atomicAdd(&s_agg[d * IN_DIM + k], nm * x[s * IN_DIM + k]);
    }
    if (t < N_NODES) {
        float nm = s_dinv[t] * s_dinv[t];
        #pragma unroll
        for (int k = 0; k < IN_DIM; k++)
            atomicAdd(&s_agg[t * IN_DIM + k], nm * x[t * IN_DIM + k]);
    }
    __syncthreads();

    for (int i = t; i < N_NODES * IN_DIM; i += 256) d_agg[i] = s_agg[i];
}

// ============================================================
// K2: pre[n][j] = relu(agg[n].Wg[:,j]+bg[j])  + fused LN partial sums
//     grid (32 j-chunks x 9 node-chunks) = 288 blocks.
// ============================================================
__global__ void __launch_bounds__(256) k_gcn(const float* __restrict__ Wg,
                                             const float* __restrict__ bg) {
    __shared__ float s_agg[N_NODES * IN_DIM];
    __shared__ float s_s[9], s_q[9];
    int t = threadIdx.x;
    for (int i = t; i < N_NODES * IN_DIM; i += 256) s_agg[i] = d_agg[i];
    if (t < 9) { s_s[t] = 0.f; s_q[t] = 0.f; }
    __syncthreads();

    int j = blockIdx.x * 256 + t;
    int n0 = blockIdx.y * 9;
    float w[IN_DIM];
    #pragma unroll
    for (int k = 0; k < IN_DIM; k++) w[k] = Wg[k * HIDDEN + j];
    float bj = bg[j];

    float ps[9], pq[9];
    #pragma unroll
    for (int nn = 0; nn < 9; nn++) {
        int n = n0 + nn;
        float acc = bj;
        #pragma unroll
        for (int k = 0; k < IN_DIM; k++)
            acc = fmaf(s_agg[n * IN_DIM + k], w[k], acc);
        float p = fmaxf(acc, 0.f);
        d_pre[n * HIDDEN + j] = p;
        ps[nn] = p;
        pq[nn] = p * p;
    }
    #pragma unroll
    for (int o = 16; o > 0; o >>= 1) {
        #pragma unroll
        for (int nn = 0; nn < 9; nn++) {
            ps[nn] += __shfl_xor_sync(0xffffffffu, ps[nn], o);
            pq[nn] += __shfl_xor_sync(0xffffffffu, pq[nn], o);
        }
    }
    if ((t & 31) == 0) {
        #pragma unroll
        for (int nn = 0; nn < 9; nn++) {
            atomicAdd(&s_s[nn], ps[nn]);
            atomicAdd(&s_q[nn], pq[nn]);
        }
    }
    __syncthreads();
    if (t < 9) {
        atomicAdd(&d_nsum[n0 + t], s_s[t]);
        atomicAdd(&d_nsq[n0 + t], s_q[t]);
    }
}

// ============================================================
// K3: pooled vector; grid 256 blocks, 32 j's per block,
//     8-way node split per j (<=11 independent scattered loads/thread).
// ============================================================
__global__ void __launch_bounds__(256) k_pool(const float* __restrict__ lng,
                                              const float* __restrict__ lnb) {
    __shared__ float s_r[N_NODES];
    __shared__ float s_rm[N_NODES];
    __shared__ float s_part[256];
    int t = threadIdx.x;
    if (t < N_NODES) {
        float mu = d_nsum[t] * (1.f / HIDDEN);
        float var = d_nsq[t] * (1.f / HIDDEN) - mu * mu;
        float r = rsqrtf(var + 1e-5f);
        s_r[t] = r;
        s_rm[t] = r * mu;
    }
    __syncthreads();
    float C = 0.f;
    #pragma unroll
    for (int n = 0; n < N_NODES; n++) C += s_rm[n];

    int tj = t & 31;
    int grp = t >> 5;                        // 0..7
    int j = blockIdx.x * 32 + tj;
    float acc = 0.f;
    #pragma unroll
    for (int n = grp; n < N_NODES; n += 8)
        acc = fmaf(s_r[n], d_pre[(size_t)n * HIDDEN + j], acc);
    s_part[t] = acc;
    __syncthreads();
    if (grp == 0) {
        float a = 0.f;
        #pragma unroll
        for (int k = 0; k < 8; k++) a += s_part[k * 32 + tj];
        d_g[j] = lng[j] * (a - C) + (float)N_NODES * lnb[j];
    }
}

// ============================================================
// K4: y1 = g @ W1   (the 256MB matvec)
//   grid (8 i-chunks x 32 j-chunks) = 256 CTAs, 256 threads.
//   Each thread: one float4 column, 256 rows (deep MLP);
//   split-K via atomicAdd (32 adds per output float).
//   L2 residency split: first PIN_CHUNKS j-chunks .ca, rest __ldcs.
// ============================================================
__global__ void __launch_bounds__(256) k_mv1(const float* __restrict__ W1) {
    __shared__ float s_g[256];
    int t = threadIdx.x;
    int j0 = blockIdx.y * 256;
    s_g[t] = d_g[j0 + t];
    __syncthreads();

    int i4 = blockIdx.x * 256 + t;               // float4 index in [0, 2048)
    const float4* W4 = (const float4*)W1;
    const float4* base = W4 + (size_t)j0 * (HIDDEN / 4) + i4;
    float4 acc = make_float4(0.f, 0.f, 0.f, 0.f);

    if (blockIdx.y < PIN_CHUNKS) {
        #pragma unroll 8
        for (int jj = 0; jj < 256; jj++) {
            float gv = s_g[jj];
            float4 w = base[(size_t)jj * (HIDDEN / 4)];
            acc.x = fmaf(gv, w.x, acc.x);
            acc.y = fmaf(gv, w.y, acc.y);
            acc.z = fmaf(gv, w.z, acc.z);
            acc.w = fmaf(gv, w.w, acc.w);
        }
    } else {
        #pragma unroll 8
        for (int jj = 0; jj < 256; jj++) {
            float gv = s_g[jj];
            float4 w = __ldcs(&base[(size_t)jj * (HIDDEN / 4)]);
            acc.x = fmaf(gv, w.x, acc.x);
            acc.y = fmaf(gv, w.y, acc.y);
            acc.z = fmaf(gv, w.z, acc.z);
            acc.w = fmaf(gv, w.w, acc.w);
        }
    }
    float* y = d_y1 + (size_t)i4 * 4;
    atomicAdd(y + 0, acc.x);
    atomicAdd(y + 1, acc.y);
    atomicAdd(y + 2, acc.z);
    atomicAdd(y + 3, acc.w);
}

// ============================================================
// K5: logits = relu(y1 + b1) @ W2   (24MB; .ca → L2-resident)
// ============================================================
__global__ void __launch_bounds__(736) k_mv2(const float* __restrict__ W2,
                                             const float* __restrict__ b1) {
    __shared__ float s_y[64];
    int t = threadIdx.x;
    int i0 = blockIdx.x * 64;
    if (t < 64) {
        float v = d_y1[i0 + t] + b1[i0 + t];
        s_y[t] = fmaxf(v, 0.f);
    }
    __syncthreads();
    if (t < ACTIONS) {
        const float* w = W2 + (size_t)i0 * ACTIONS + t;
        float acc = 0.f;
        #pragma unroll 8
        for (int ii = 0; ii < 64; ii++)
            acc = fmaf(s_y[ii], __ldg(w + (size_t)ii * ACTIONS), acc);
        atomicAdd(&d_logits[t], acc);
    }
}

// ============================================================
// K6: add b2, log_softmax, write output
// ============================================================
__global__ void __launch_bounds__(1024) k_out(const float* __restrict__ b2,
                                              float* __restrict__ out) {
    __shared__ float sh[1024];
    int t = threadIdx.x;
    float l = (t < ACTIONS) ? d_logits[t] + b2[t] : -1e30f;
    sh[t] = l;
    __syncthreads();
    for (int s = 512; s > 0; s >>= 1) {
        if (t < s) sh[t] = fmaxf(sh[t], sh[t + s]);
        __syncthreads();
    }
    float m = sh[0];
    __syncthreads();
    float e = (t < ACTIONS) ? expf(l - m) : 0.f;
    sh[t] = e;
    __syncthreads();
    for (int s = 512; s > 0; s >>= 1) {
        if (t < s) sh[t] += sh[t + s];
        __syncthreads();
    }
    float lse = logf(sh[0]);
    if (t < ACTIONS) out[t] = l - m - lse;
}

// ============================================================
extern "C" void kernel_launch(void* const* d_in, const int* in_sizes, int n_in,
                              void* d_out, int out_size) {
    const float* x   = (const float*)d_in[0];
    const int*   ei  = (const int*)d_in[1];     // int32 or int64 (detected)
    const float* Wg  = (const float*)d_in[2];
    const float* bg  = (const float*)d_in[3];
    const float* lng = (const float*)d_in[4];
    const float* lnb = (const float*)d_in[5];
    const float* W1  = (const float*)d_in[6];
    const float* b1  = (const float*)d_in[7];
    const float* W2  = (const float*)d_in[8];
    const float* b2  = (const float*)d_in[9];
    float* out = (float*)d_out;

    k_setup<<<1, 256>>>(x, ei);
    k_gcn<<<dim3(32, 9), 256>>>(Wg, bg);
    k_pool<<<256, 256>>>(lng, lnb);
    k_mv1<<<dim3(8, 32), 256>>>(W1);
    k_mv2<<<128, 736>>>(W2, b1);
    k_out<<<1, 1024>>>(b2, out);
}